// round 8
// baseline (speedup 1.0000x reference)
#include <cuda_runtime.h>

#define NE 32
#define NUP 16
#define NA 8
#define DF 32
#define WH 16
#define KD 8
#define ED 16

typedef unsigned long long ull;

// ---- shared memory layout (float offsets, 16B-aligned) ----
#define OFF_W1   0        // [2][3][32][16] = 3072
#define OFF_B1   3072     // [2][3][16]     = 96
#define OFF_W2   3168     // [2][3][16][8]  = 768
#define OFF_B2   3936     // [2][3][8]      = 48
#define OFF_HW   3984     // [2][16][8]     = 256
#define OFF_HB   4240     // [2][8]         = 16
#define OFF_GW   4256     // [2][8][16]     = 256
#define OFF_GB   4512     // [2][16]        = 32
#define OFF_ORB  4544     // [16]
#define OFF_XE   4560     // [2][16]        = 32
#define OFF_Y    4592     // [8][8]         = 64
#define OFF_X    4656     // [32][16]       = 512
#define OFF_HX   5168     // [32][8]        = 256
#define OFF_Z0   5424     // [32][8]        = 256
#define OFF_Z1   5680     // [32][8]        = 256
#define OFF_WF1  5936     // [32][32][8]    = 8192  (layer-1 elec filters)
#define OFF_RED  14128
#define SMEM_FLOATS 14132

__device__ __forceinline__ void fma2(ull& d, ull a, ull b) {
    asm("fma.rn.f32x2 %0, %1, %2, %0;" : "+l"(d) : "l"(a), "l"(b));
}
__device__ __forceinline__ ull dup2(float x) {
    unsigned u = __float_as_uint(x);
    ull r; asm("mov.b64 %0, {%1, %2};" : "=l"(r) : "r"(u), "r"(u));
    return r;
}
__device__ __forceinline__ float2 unp2(ull p) {
    unsigned lo, hi;
    asm("mov.b64 {%0, %1}, %2;" : "=r"(lo), "=r"(hi) : "l"(p));
    return make_float2(__uint_as_float(lo), __uint_as_float(hi));
}
// ssp(x) = softplus(x) - ln2; inputs bounded, approx MUFU path
__device__ __forceinline__ float sspf(float x) {
    float t; asm("ex2.approx.ftz.f32 %0, %1;" : "=f"(t) : "f"(x * 1.4426950408889634f));
    float u; asm("lg2.approx.ftz.f32 %0, %1;" : "=f"(u) : "f"(1.0f + t));
    return fmaf(0.69314718055994531f, u, -0.69314718055994531f);
}

// ---- filter MLP on TWO edges sharing one weight stream ----
// Edge features are STREAMED from global (pA/pB), not held across calls.
// ssp + W2 fused into the h-unpack loop to minimize live registers.
__device__ __forceinline__ void mlp_pair_g(const float4* __restrict__ pA,
                                           const float4* __restrict__ pB,
                                           const float* s, int sk,
                                           float* mA, float* mB)
{
    const float* w1  = s + OFF_W1 + (sk << 9);
    const ull*   b1p = (const ull*)(s + OFF_B1 + (sk << 4));
    ull hA[8], hB[8];
    #pragma unroll
    for (int t = 0; t < 8; t++) { hA[t] = b1p[t]; hB[t] = hA[t]; }
    #pragma unroll
    for (int u = 0; u < 8; u++) {
        float4 a4 = pA[u], b4 = pB[u];
        #pragma unroll
        for (int fi = 0; fi < 4; fi++) {
            float fa = (fi == 0) ? a4.x : (fi == 1) ? a4.y : (fi == 2) ? a4.z : a4.w;
            float fb = (fi == 0) ? b4.x : (fi == 1) ? b4.y : (fi == 2) ? b4.z : b4.w;
            ull pa = dup2(fa), pb = dup2(fb);
            const ulonglong2* wr = (const ulonglong2*)(w1 + ((u * 4 + fi) << 4));
            ulonglong2 w0 = wr[0], w1v = wr[1], w2v = wr[2], w3 = wr[3];
            fma2(hA[0], pa, w0.x);  fma2(hB[0], pb, w0.x);
            fma2(hA[1], pa, w0.y);  fma2(hB[1], pb, w0.y);
            fma2(hA[2], pa, w1v.x); fma2(hB[2], pb, w1v.x);
            fma2(hA[3], pa, w1v.y); fma2(hB[3], pb, w1v.y);
            fma2(hA[4], pa, w2v.x); fma2(hB[4], pb, w2v.x);
            fma2(hA[5], pa, w2v.y); fma2(hB[5], pb, w2v.y);
            fma2(hA[6], pa, w3.x);  fma2(hB[6], pb, w3.x);
            fma2(hA[7], pa, w3.y);  fma2(hB[7], pb, w3.y);
        }
    }
    // fused ssp + layer-2 (16 -> 8)
    const float* w2  = s + OFF_W2 + (sk << 7);
    const ull*   b2p = (const ull*)(s + OFF_B2 + (sk << 3));
    ull oA[4], oB[4];
    #pragma unroll
    for (int t = 0; t < 4; t++) { oA[t] = b2p[t]; oB[t] = oA[t]; }
    #pragma unroll
    for (int t = 0; t < 8; t++) {
        float2 va = unp2(hA[t]), vb = unp2(hB[t]);
        float a0 = sspf(va.x), a1 = sspf(va.y);
        float b0 = sspf(vb.x), b1 = sspf(vb.y);
        const ulonglong2* wr0 = (const ulonglong2*)(w2 + ((2 * t) << 3));
        ulonglong2 x0 = wr0[0], x1 = wr0[1];
        ull pa = dup2(a0), pb = dup2(b0);
        fma2(oA[0], pa, x0.x); fma2(oB[0], pb, x0.x);
        fma2(oA[1], pa, x0.y); fma2(oB[1], pb, x0.y);
        fma2(oA[2], pa, x1.x); fma2(oB[2], pb, x1.x);
        fma2(oA[3], pa, x1.y); fma2(oB[3], pb, x1.y);
        const ulonglong2* wr1 = (const ulonglong2*)(w2 + ((2 * t + 1) << 3));
        ulonglong2 y0 = wr1[0], y1 = wr1[1];
        pa = dup2(a1); pb = dup2(b1);
        fma2(oA[0], pa, y0.x); fma2(oB[0], pb, y0.x);
        fma2(oA[1], pa, y0.y); fma2(oB[1], pb, y0.y);
        fma2(oA[2], pa, y1.x); fma2(oB[2], pb, y1.x);
        fma2(oA[3], pa, y1.y); fma2(oB[3], pb, y1.y);
    }
    #pragma unroll
    for (int t = 0; t < 4; t++) {
        float2 va = unp2(oA[t]), vb = unp2(oB[t]);
        mA[2*t] = sspf(va.x); mA[2*t+1] = sspf(va.y);
        mB[2*t] = sspf(vb.x); mB[2*t+1] = sspf(vb.y);
    }
}

// ---- single-edge variant (nuclear channel), streamed + fused ----
__device__ __forceinline__ void mlp_one_g(const float4* __restrict__ pE,
                                          const float* s, int sk, float* m)
{
    const float* w1  = s + OFF_W1 + (sk << 9);
    const ull*   b1p = (const ull*)(s + OFF_B1 + (sk << 4));
    ull h1[8];
    #pragma unroll
    for (int t = 0; t < 8; t++) h1[t] = b1p[t];
    #pragma unroll
    for (int u = 0; u < 8; u++) {
        float4 e4 = pE[u];
        #pragma unroll
        for (int fi = 0; fi < 4; fi++) {
            float ef = (fi == 0) ? e4.x : (fi == 1) ? e4.y : (fi == 2) ? e4.z : e4.w;
            ull ep = dup2(ef);
            const ulonglong2* wr = (const ulonglong2*)(w1 + ((u * 4 + fi) << 4));
            ulonglong2 w0 = wr[0], w1v = wr[1], w2v = wr[2], w3 = wr[3];
            fma2(h1[0], ep, w0.x);  fma2(h1[1], ep, w0.y);
            fma2(h1[2], ep, w1v.x); fma2(h1[3], ep, w1v.y);
            fma2(h1[4], ep, w2v.x); fma2(h1[5], ep, w2v.y);
            fma2(h1[6], ep, w3.x);  fma2(h1[7], ep, w3.y);
        }
    }
    const float* w2  = s + OFF_W2 + (sk << 7);
    const ull*   b2p = (const ull*)(s + OFF_B2 + (sk << 3));
    ull o2[4];
    #pragma unroll
    for (int t = 0; t < 4; t++) o2[t] = b2p[t];
    #pragma unroll
    for (int t = 0; t < 8; t++) {
        float2 v = unp2(h1[t]);
        float a0 = sspf(v.x), a1 = sspf(v.y);
        const ulonglong2* wr0 = (const ulonglong2*)(w2 + ((2 * t) << 3));
        ulonglong2 x0 = wr0[0], x1 = wr0[1];
        ull pa = dup2(a0);
        fma2(o2[0], pa, x0.x); fma2(o2[1], pa, x0.y);
        fma2(o2[2], pa, x1.x); fma2(o2[3], pa, x1.y);
        const ulonglong2* wr1 = (const ulonglong2*)(w2 + ((2 * t + 1) << 3));
        ulonglong2 y0 = wr1[0], y1 = wr1[1];
        pa = dup2(a1);
        fma2(o2[0], pa, y0.x); fma2(o2[1], pa, y0.y);
        fma2(o2[2], pa, y1.x); fma2(o2[3], pa, y1.y);
    }
    #pragma unroll
    for (int t = 0; t < 4; t++) {
        float2 v = unp2(o2[t]);
        m[2*t] = sspf(v.x); m[2*t+1] = sspf(v.y);
    }
}

__global__ void __launch_bounds__(256, 3)
jastrow_kernel(const float* __restrict__ ee,   // [B,32,32,32]
               const float* __restrict__ en,   // [B,32,8,32]
               const float* __restrict__ Xemb,
               const float* __restrict__ Yv,
               const float* __restrict__ wW1,
               const float* __restrict__ wb1,
               const float* __restrict__ wW2,
               const float* __restrict__ wb2,
               const float* __restrict__ hW,
               const float* __restrict__ hb,
               const float* __restrict__ gW,
               const float* __restrict__ gb,
               const float* __restrict__ orbW,
               float* __restrict__ out)
{
    extern __shared__ float s[];
    const int tid  = threadIdx.x;
    const int lane = tid & 31;
    const int b    = blockIdx.x;

    for (int t = tid; t < 3072; t += 256) s[OFF_W1 + t] = wW1[t];
    for (int t = tid; t < 96;   t += 256) s[OFF_B1 + t] = wb1[t];
    for (int t = tid; t < 768;  t += 256) s[OFF_W2 + t] = wW2[t];
    for (int t = tid; t < 48;   t += 256) s[OFF_B2 + t] = wb2[t];
    for (int t = tid; t < 256;  t += 256) s[OFF_HW + t] = hW[t];
    for (int t = tid; t < 16;   t += 256) s[OFF_HB + t] = hb[t];
    for (int t = tid; t < 256;  t += 256) s[OFF_GW + t] = gW[t];
    for (int t = tid; t < 32;   t += 256) s[OFF_GB + t] = gb[t];
    for (int t = tid; t < 16;   t += 256) s[OFF_ORB + t] = orbW[t];
    for (int t = tid; t < 32;   t += 256) s[OFF_XE + t] = Xemb[t];
    for (int t = tid; t < 64;   t += 256) s[OFF_Y + t]  = Yv[t];
    s[OFF_Z0 + tid] = 0.f;
    s[OFF_Z1 + tid] = 0.f;
    if (tid == 0) s[OFF_RED] = 0.f;
    // init x[i][e] = X_emb[spin(i)][e]
    for (int t = tid; t < NE * ED; t += 256) {
        int i = t >> 4;
        s[OFF_X + t] = Xemb[((i >= NUP) ? ED : 0) + (t & 15)];
    }
    __syncthreads();

    // hx0[j][k] = ssp(x0[j] @ hW0 + hb0)
    {
        int j = tid >> 3, k = tid & 7;
        float a = s[OFF_HB + k];
        #pragma unroll
        for (int ei = 0; ei < ED; ei++)
            a = fmaf(s[OFF_X + j * ED + ei], s[OFF_HW + ei * KD + k], a);
        s[OFF_HX + tid] = sspf(a);
    }
    __syncthreads();

    // ============ edge phase: elec pairs, both layers (features re-streamed) ====
    const int q = tid;

    #pragma unroll 1
    for (int p = 0; p < 2; p++) {
        int iA, jA, iB, jB;
        float maskA = 1.f, maskB = 1.f;
        if (p == 0) {
            iA = q >> 4;        jA = q & 15;
            iB = 16 + (q >> 4); jB = 16 + (q & 15);
            if (iA == jA) { maskA = 0.f; maskB = 0.f; }
        } else {
            iA = q >> 4;        jA = 16 + (q & 15);
            iB = 16 + (q >> 4); jB = q & 15;
        }
        const float4* pA = (const float4*)(ee + (((size_t)b * NE + iA) * NE + jA) * DF);
        const float4* pB = (const float4*)(ee + (((size_t)b * NE + iB) * NE + jB) * DF);

        #pragma unroll 1
        for (int l = 0; l < 2; l++) {
            float mA[8], mB[8];
            mlp_pair_g(pA, pB, s, l * 3 + p, mA, mB);
            if (l == 0) {
                const float4* hxA = (const float4*)(s + OFF_HX + (jA << 3));
                const float4* hxB = (const float4*)(s + OFF_HX + (jB << 3));
                float4 a0 = hxA[0], a1 = hxA[1], b0 = hxB[0], b1 = hxB[1];
                mA[0] *= a0.x * maskA; mA[1] *= a0.y * maskA;
                mA[2] *= a0.z * maskA; mA[3] *= a0.w * maskA;
                mA[4] *= a1.x * maskA; mA[5] *= a1.y * maskA;
                mA[6] *= a1.z * maskA; mA[7] *= a1.w * maskA;
                mB[0] *= b0.x * maskB; mB[1] *= b0.y * maskB;
                mB[2] *= b0.z * maskB; mB[3] *= b0.w * maskB;
                mB[4] *= b1.x * maskB; mB[5] *= b1.y * maskB;
                mB[6] *= b1.z * maskB; mB[7] *= b1.w * maskB;
                #pragma unroll
                for (int k = 0; k < 8; k++) {
                    #pragma unroll
                    for (int d = 1; d < 16; d <<= 1) {
                        mA[k] += __shfl_xor_sync(0xffffffffu, mA[k], d);
                        mB[k] += __shfl_xor_sync(0xffffffffu, mB[k], d);
                    }
                }
                if ((lane & 15) == 0) {
                    #pragma unroll
                    for (int k = 0; k < 8; k++) {
                        atomicAdd(&s[OFF_Z0 + (iA << 3) + k], mA[k]);
                        atomicAdd(&s[OFF_Z0 + (iB << 3) + k], mB[k]);
                    }
                }
            } else {
                float4* dA = (float4*)(s + OFF_WF1 + (((iA << 5) + jA) << 3));
                float4* dB = (float4*)(s + OFF_WF1 + (((iB << 5) + jB) << 3));
                dA[0] = make_float4(mA[0]*maskA, mA[1]*maskA, mA[2]*maskA, mA[3]*maskA);
                dA[1] = make_float4(mA[4]*maskA, mA[5]*maskA, mA[6]*maskA, mA[7]*maskA);
                dB[0] = make_float4(mB[0]*maskB, mB[1]*maskB, mB[2]*maskB, mB[3]*maskB);
                dB[1] = make_float4(mB[4]*maskB, mB[5]*maskB, mB[6]*maskB, mB[7]*maskB);
            }
        }
    }

    // ---- nuclear edges: i = q>>3, atom = q&7, c=2; both layers contract with Y
    {
        int i = q >> 3, jm = q & 7;
        const float4* pN = (const float4*)(en + (((size_t)b * NE + i) * NA + jm) * DF);
        const float4* yr = (const float4*)(s + OFF_Y + (jm << 3));
        float4 y0 = yr[0], y1 = yr[1];
        #pragma unroll 1
        for (int l = 0; l < 2; l++) {
            float m0[8], m1[8];
            mlp_one_g(pN, s, l * 3 + 2, m0);
            m1[0] = m0[0]*y0.x; m1[1] = m0[1]*y0.y; m1[2] = m0[2]*y0.z; m1[3] = m0[3]*y0.w;
            m1[4] = m0[4]*y1.x; m1[5] = m0[5]*y1.y; m1[6] = m0[6]*y1.z; m1[7] = m0[7]*y1.w;
            #pragma unroll
            for (int k = 0; k < 8; k++) {
                #pragma unroll
                for (int d = 1; d < 8; d <<= 1)
                    m1[k] += __shfl_xor_sync(0xffffffffu, m1[k], d);
            }
            if ((lane & 7) == 0) {
                float* zdst = s + ((l == 0) ? OFF_Z0 : OFF_Z1) + (i << 3);
                #pragma unroll
                for (int k = 0; k < 8; k++) atomicAdd(&zdst[k], m1[k]);
            }
        }
    }
    __syncthreads();

    // ============ layer-0 update: x += Z0 @ gW0 + gb0 ============
    for (int t = tid; t < NE * ED; t += 256) {
        int i = t >> 4, ei = t & 15;
        float a = s[OFF_GB + ei];
        #pragma unroll
        for (int k = 0; k < KD; k++)
            a = fmaf(s[OFF_Z0 + i * KD + k], s[OFF_GW + k * ED + ei], a);
        s[OFF_X + t] += a;
    }
    __syncthreads();

    // hx1[j][k] = ssp(x1[j] @ hW1 + hb1)
    {
        int j = tid >> 3, k = tid & 7;
        float a = s[OFF_HB + KD + k];
        #pragma unroll
        for (int ei = 0; ei < ED; ei++)
            a = fmaf(s[OFF_X + j * ED + ei], s[OFF_HW + (ED + ei) * KD + k], a);
        s[OFF_HX + tid] = sspf(a);
    }
    __syncthreads();

    // z1[i][k] += sum_j WF1[i][j][k] * hx1[j][k]   (Z1 already has nuc part)
    {
        int i = tid >> 3, k = tid & 7;
        float a = s[OFF_Z1 + tid];
        const float* wf = s + OFF_WF1 + (i << 8) + k;
        #pragma unroll
        for (int j = 0; j < NE; j++)
            a = fmaf(wf[j << 3], s[OFF_HX + (j << 3) + k], a);
        s[OFF_Z1 + tid] = a;
    }
    __syncthreads();

    // layer-1 update: x += Z1 @ gW1 + gb1
    for (int t = tid; t < NE * ED; t += 256) {
        int i = t >> 4, ei = t & 15;
        float a = s[OFF_GB + ED + ei];
        #pragma unroll
        for (int k = 0; k < KD; k++)
            a = fmaf(s[OFF_Z1 + i * KD + k], s[OFF_GW + (KD + k) * ED + ei], a);
        s[OFF_X + t] += a;
    }
    __syncthreads();

    // readout
    float part = 0.f;
    for (int t = tid; t < NE * ED; t += 256)
        part += s[OFF_X + t] * s[OFF_ORB + (t & 15)];
    #pragma unroll
    for (int off = 16; off > 0; off >>= 1)
        part += __shfl_down_sync(0xffffffffu, part, off);
    if (lane == 0) atomicAdd(&s[OFF_RED], part);
    __syncthreads();
    if (tid == 0) out[b] = s[OFF_RED];
}

extern "C" void kernel_launch(void* const* d_in, const int* in_sizes, int n_in,
                              void* d_out, int out_size) {
    const float* ee   = (const float*)d_in[0];
    const float* en   = (const float*)d_in[1];
    const float* Xemb = (const float*)d_in[2];
    const float* Yv   = (const float*)d_in[3];
    const float* wW1  = (const float*)d_in[4];
    const float* wb1  = (const float*)d_in[5];
    const float* wW2  = (const float*)d_in[6];
    const float* wb2  = (const float*)d_in[7];
    const float* hW   = (const float*)d_in[8];
    const float* hb   = (const float*)d_in[9];
    const float* gW   = (const float*)d_in[10];
    const float* gb   = (const float*)d_in[11];
    const float* orbW = (const float*)d_in[12];
    float* out = (float*)d_out;

    size_t smem = SMEM_FLOATS * sizeof(float);
    cudaFuncSetAttribute(jastrow_kernel,
                         cudaFuncAttributeMaxDynamicSharedMemorySize, (int)smem);
    jastrow_kernel<<<512, 256, smem>>>(ee, en, Xemb, Yv, wW1, wb1, wW2, wb2,
                                       hW, hb, gW, gb, orbW, out);
}

// round 9
// speedup vs baseline: 2.0076x; 2.0076x over previous
#include <cuda_runtime.h>

#define NE 32
#define NUP 16
#define NA 8
#define DF 32
#define WH 16
#define KD 8
#define ED 16

typedef unsigned long long ull;

// ---- shared memory layout (float offsets, 16B-aligned) ----
#define OFF_W1   0        // [2][3][32][16] = 3072
#define OFF_B1   3072     // [2][3][16]     = 96
#define OFF_W2   3168     // [2][3][16][8]  = 768
#define OFF_B2   3936     // [2][3][8]      = 48
#define OFF_HW   3984     // [2][16][8]     = 256
#define OFF_HB   4240     // [2][8]         = 16
#define OFF_GW   4256     // [2][8][16]     = 256
#define OFF_GB   4512     // [2][16]        = 32
#define OFF_ORB  4544     // [16]
#define OFF_XE   4560     // [2][16]        = 32
#define OFF_Y    4592     // [8][8]         = 64
#define OFF_X    4656     // [32][16]       = 512
#define OFF_HX   5168     // [32][8]        = 256
#define OFF_Z0   5424     // [32][8]        = 256
#define OFF_Z1   5680     // [32][8]        = 256
#define OFF_WF1  5936     // [32][32][8]    = 8192  (layer-1 elec filters)
#define OFF_RED  14128
#define SMEM_FLOATS 14132

__device__ __forceinline__ void fma2(ull& d, ull a, ull b) {
    asm("fma.rn.f32x2 %0, %1, %2, %0;" : "+l"(d) : "l"(a), "l"(b));
}
__device__ __forceinline__ ull dup2(float x) {
    unsigned u = __float_as_uint(x);
    ull r; asm("mov.b64 %0, {%1, %2};" : "=l"(r) : "r"(u), "r"(u));
    return r;
}
__device__ __forceinline__ float2 unp2(ull p) {
    unsigned lo, hi;
    asm("mov.b64 {%0, %1}, %2;" : "=r"(lo), "=r"(hi) : "l"(p));
    return make_float2(__uint_as_float(lo), __uint_as_float(hi));
}
// ssp(x) = softplus(x) - ln2; inputs bounded, approx MUFU path
__device__ __forceinline__ float sspf(float x) {
    float t; asm("ex2.approx.ftz.f32 %0, %1;" : "=f"(t) : "f"(x * 1.4426950408889634f));
    float u; asm("lg2.approx.ftz.f32 %0, %1;" : "=f"(u) : "f"(1.0f + t));
    return fmaf(0.69314718055994531f, u, -0.69314718055994531f);
}

// ---- layer-1 accumulate for TWO register-resident edges, shared weight stream ----
__device__ __forceinline__ void h1_pair(const float4* evA, const float4* evB,
                                        const float* s, int sk, ull* hA, ull* hB)
{
    const float* w1  = s + OFF_W1 + (sk << 9);
    const ull*   b1p = (const ull*)(s + OFF_B1 + (sk << 4));
    #pragma unroll
    for (int t = 0; t < 8; t++) { hA[t] = b1p[t]; hB[t] = hA[t]; }
    #pragma unroll
    for (int u = 0; u < 8; u++) {
        float4 a4 = evA[u], b4 = evB[u];
        #pragma unroll
        for (int fi = 0; fi < 4; fi++) {
            float fa = (fi == 0) ? a4.x : (fi == 1) ? a4.y : (fi == 2) ? a4.z : a4.w;
            float fb = (fi == 0) ? b4.x : (fi == 1) ? b4.y : (fi == 2) ? b4.z : b4.w;
            ull pa = dup2(fa), pb = dup2(fb);
            const ulonglong2* wr = (const ulonglong2*)(w1 + ((u * 4 + fi) << 4));
            ulonglong2 w0 = wr[0], w1v = wr[1], w2v = wr[2], w3 = wr[3];
            fma2(hA[0], pa, w0.x);  fma2(hB[0], pb, w0.x);
            fma2(hA[1], pa, w0.y);  fma2(hB[1], pb, w0.y);
            fma2(hA[2], pa, w1v.x); fma2(hB[2], pb, w1v.x);
            fma2(hA[3], pa, w1v.y); fma2(hB[3], pb, w1v.y);
            fma2(hA[4], pa, w2v.x); fma2(hB[4], pb, w2v.x);
            fma2(hA[5], pa, w2v.y); fma2(hB[5], pb, w2v.y);
            fma2(hA[6], pa, w3.x);  fma2(hB[6], pb, w3.x);
            fma2(hA[7], pa, w3.y);  fma2(hB[7], pb, w3.y);
        }
    }
}

// ---- fused ssp + layer-2 (16 -> 8) + output ssp for two edges ----
__device__ __forceinline__ void finish_pair(const ull* hA, const ull* hB,
                                            const float* s, int sk,
                                            float* mA, float* mB)
{
    const float* w2  = s + OFF_W2 + (sk << 7);
    const ull*   b2p = (const ull*)(s + OFF_B2 + (sk << 3));
    ull oA[4], oB[4];
    #pragma unroll
    for (int t = 0; t < 4; t++) { oA[t] = b2p[t]; oB[t] = oA[t]; }
    #pragma unroll
    for (int t = 0; t < 8; t++) {
        float2 va = unp2(hA[t]), vb = unp2(hB[t]);
        float a0 = sspf(va.x), a1 = sspf(va.y);
        float b0 = sspf(vb.x), b1 = sspf(vb.y);
        const ulonglong2* wr0 = (const ulonglong2*)(w2 + ((2 * t) << 3));
        ulonglong2 x0 = wr0[0], x1 = wr0[1];
        ull pa = dup2(a0), pb = dup2(b0);
        fma2(oA[0], pa, x0.x); fma2(oB[0], pb, x0.x);
        fma2(oA[1], pa, x0.y); fma2(oB[1], pb, x0.y);
        fma2(oA[2], pa, x1.x); fma2(oB[2], pb, x1.x);
        fma2(oA[3], pa, x1.y); fma2(oB[3], pb, x1.y);
        const ulonglong2* wr1 = (const ulonglong2*)(w2 + ((2 * t + 1) << 3));
        ulonglong2 y0 = wr1[0], y1 = wr1[1];
        pa = dup2(a1); pb = dup2(b1);
        fma2(oA[0], pa, y0.x); fma2(oB[0], pb, y0.x);
        fma2(oA[1], pa, y0.y); fma2(oB[1], pb, y0.y);
        fma2(oA[2], pa, y1.x); fma2(oB[2], pb, y1.x);
        fma2(oA[3], pa, y1.y); fma2(oB[3], pb, y1.y);
    }
    #pragma unroll
    for (int t = 0; t < 4; t++) {
        float2 va = unp2(oA[t]), vb = unp2(oB[t]);
        mA[2*t] = sspf(va.x); mA[2*t+1] = sspf(va.y);
        mB[2*t] = sspf(vb.x); mB[2*t+1] = sspf(vb.y);
    }
}

// ---- single-edge variants (nuclear channel) ----
__device__ __forceinline__ void h1_one(const float4* ev, const float* s, int sk, ull* h1)
{
    const float* w1  = s + OFF_W1 + (sk << 9);
    const ull*   b1p = (const ull*)(s + OFF_B1 + (sk << 4));
    #pragma unroll
    for (int t = 0; t < 8; t++) h1[t] = b1p[t];
    #pragma unroll
    for (int u = 0; u < 8; u++) {
        float4 e4 = ev[u];
        #pragma unroll
        for (int fi = 0; fi < 4; fi++) {
            float ef = (fi == 0) ? e4.x : (fi == 1) ? e4.y : (fi == 2) ? e4.z : e4.w;
            ull ep = dup2(ef);
            const ulonglong2* wr = (const ulonglong2*)(w1 + ((u * 4 + fi) << 4));
            ulonglong2 w0 = wr[0], w1v = wr[1], w2v = wr[2], w3 = wr[3];
            fma2(h1[0], ep, w0.x);  fma2(h1[1], ep, w0.y);
            fma2(h1[2], ep, w1v.x); fma2(h1[3], ep, w1v.y);
            fma2(h1[4], ep, w2v.x); fma2(h1[5], ep, w2v.y);
            fma2(h1[6], ep, w3.x);  fma2(h1[7], ep, w3.y);
        }
    }
}
__device__ __forceinline__ void finish_one(const ull* h1, const float* s, int sk, float* m)
{
    const float* w2  = s + OFF_W2 + (sk << 7);
    const ull*   b2p = (const ull*)(s + OFF_B2 + (sk << 3));
    ull o2[4];
    #pragma unroll
    for (int t = 0; t < 4; t++) o2[t] = b2p[t];
    #pragma unroll
    for (int t = 0; t < 8; t++) {
        float2 v = unp2(h1[t]);
        float a0 = sspf(v.x), a1 = sspf(v.y);
        const ulonglong2* wr0 = (const ulonglong2*)(w2 + ((2 * t) << 3));
        ulonglong2 x0 = wr0[0], x1 = wr0[1];
        ull pa = dup2(a0);
        fma2(o2[0], pa, x0.x); fma2(o2[1], pa, x0.y);
        fma2(o2[2], pa, x1.x); fma2(o2[3], pa, x1.y);
        const ulonglong2* wr1 = (const ulonglong2*)(w2 + ((2 * t + 1) << 3));
        ulonglong2 y0 = wr1[0], y1 = wr1[1];
        pa = dup2(a1);
        fma2(o2[0], pa, y0.x); fma2(o2[1], pa, y0.y);
        fma2(o2[2], pa, y1.x); fma2(o2[3], pa, y1.y);
    }
    #pragma unroll
    for (int t = 0; t < 4; t++) {
        float2 v = unp2(o2[t]);
        m[2*t] = sspf(v.x); m[2*t+1] = sspf(v.y);
    }
}

// layer-0 elec epilogue: mask+hx multiply, 16-lane reduce, atomic scatter into Z0
__device__ __forceinline__ void reduce_scatter_l0(float* s, int lane,
                                                  int iA, int jA, int iB, int jB,
                                                  float maskA, float maskB,
                                                  float* mA, float* mB)
{
    const float4* hxA = (const float4*)(s + OFF_HX + (jA << 3));
    const float4* hxB = (const float4*)(s + OFF_HX + (jB << 3));
    float4 a0 = hxA[0], a1 = hxA[1], b0 = hxB[0], b1 = hxB[1];
    mA[0] *= a0.x * maskA; mA[1] *= a0.y * maskA;
    mA[2] *= a0.z * maskA; mA[3] *= a0.w * maskA;
    mA[4] *= a1.x * maskA; mA[5] *= a1.y * maskA;
    mA[6] *= a1.z * maskA; mA[7] *= a1.w * maskA;
    mB[0] *= b0.x * maskB; mB[1] *= b0.y * maskB;
    mB[2] *= b0.z * maskB; mB[3] *= b0.w * maskB;
    mB[4] *= b1.x * maskB; mB[5] *= b1.y * maskB;
    mB[6] *= b1.z * maskB; mB[7] *= b1.w * maskB;
    #pragma unroll
    for (int k = 0; k < 8; k++) {
        #pragma unroll
        for (int d = 1; d < 16; d <<= 1) {
            mA[k] += __shfl_xor_sync(0xffffffffu, mA[k], d);
            mB[k] += __shfl_xor_sync(0xffffffffu, mB[k], d);
        }
    }
    if ((lane & 15) == 0) {
        #pragma unroll
        for (int k = 0; k < 8; k++) {
            atomicAdd(&s[OFF_Z0 + (iA << 3) + k], mA[k]);
            atomicAdd(&s[OFF_Z0 + (iB << 3) + k], mB[k]);
        }
    }
}

__device__ __forceinline__ void store_wf1(float* s, int i, int j, float mask, const float* m)
{
    float4* d = (float4*)(s + OFF_WF1 + (((i << 5) + j) << 3));
    d[0] = make_float4(m[0]*mask, m[1]*mask, m[2]*mask, m[3]*mask);
    d[1] = make_float4(m[4]*mask, m[5]*mask, m[6]*mask, m[7]*mask);
}

__global__ void __launch_bounds__(256, 2)
jastrow_kernel(const float* __restrict__ ee,   // [B,32,32,32]
               const float* __restrict__ en,   // [B,32,8,32]
               const float* __restrict__ Xemb,
               const float* __restrict__ Yv,
               const float* __restrict__ wW1,
               const float* __restrict__ wb1,
               const float* __restrict__ wW2,
               const float* __restrict__ wb2,
               const float* __restrict__ hW,
               const float* __restrict__ hb,
               const float* __restrict__ gW,
               const float* __restrict__ gb,
               const float* __restrict__ orbW,
               float* __restrict__ out)
{
    extern __shared__ float s[];
    const int tid  = threadIdx.x;
    const int lane = tid & 31;
    const int b    = blockIdx.x;

    for (int t = tid; t < 3072; t += 256) s[OFF_W1 + t] = wW1[t];
    for (int t = tid; t < 96;   t += 256) s[OFF_B1 + t] = wb1[t];
    for (int t = tid; t < 768;  t += 256) s[OFF_W2 + t] = wW2[t];
    for (int t = tid; t < 48;   t += 256) s[OFF_B2 + t] = wb2[t];
    for (int t = tid; t < 256;  t += 256) s[OFF_HW + t] = hW[t];
    for (int t = tid; t < 16;   t += 256) s[OFF_HB + t] = hb[t];
    for (int t = tid; t < 256;  t += 256) s[OFF_GW + t] = gW[t];
    for (int t = tid; t < 32;   t += 256) s[OFF_GB + t] = gb[t];
    for (int t = tid; t < 16;   t += 256) s[OFF_ORB + t] = orbW[t];
    for (int t = tid; t < 32;   t += 256) s[OFF_XE + t] = Xemb[t];
    for (int t = tid; t < 64;   t += 256) s[OFF_Y + t]  = Yv[t];
    s[OFF_Z0 + tid] = 0.f;
    s[OFF_Z1 + tid] = 0.f;
    if (tid == 0) s[OFF_RED] = 0.f;
    // init x[i][e] = X_emb[spin(i)][e]
    for (int t = tid; t < NE * ED; t += 256) {
        int i = t >> 4;
        s[OFF_X + t] = Xemb[((i >= NUP) ? ED : 0) + (t & 15)];
    }
    __syncthreads();

    // hx0[j][k] = ssp(x0[j] @ hW0 + hb0)
    {
        int j = tid >> 3, k = tid & 7;
        float a = s[OFF_HB + k];
        #pragma unroll
        for (int ei = 0; ei < ED; ei++)
            a = fmaf(s[OFF_X + j * ED + ei], s[OFF_HW + ei * KD + k], a);
        s[OFF_HX + tid] = sspf(a);
    }
    __syncthreads();

    // ============ edge phase (straight-line, prefetched) ============
    const int q = tid;
    // p0 indices (same-spin, channel 0)
    const int iA0 = q >> 4,        jA0 = q & 15;
    const int iB0 = 16 + (q >> 4), jB0 = 16 + (q & 15);
    const float mk0 = (iA0 == jA0) ? 0.f : 1.f;
    // p1 indices (anti-spin, channel 1)
    const int iA1 = q >> 4,        jA1 = 16 + (q & 15);
    const int iB1 = 16 + (q >> 4), jB1 = q & 15;
    // nuc indices
    const int iN = q >> 3, jN = q & 7;

    float4 evA[8], evB[8];
    ull hA[8], hB[8];
    float mA[8], mB[8];

    // ---- load p0 edges (batched: 16 independent LDG.128)
    {
        const float4* pA = (const float4*)(ee + (((size_t)b * NE + iA0) * NE + jA0) * DF);
        const float4* pB = (const float4*)(ee + (((size_t)b * NE + iB0) * NE + jB0) * DF);
        #pragma unroll
        for (int u = 0; u < 8; u++) { evA[u] = pA[u]; evB[u] = pB[u]; }
    }

    // ---- p0 layer 0 (sk=0)
    h1_pair(evA, evB, s, 0, hA, hB);
    finish_pair(hA, hB, s, 0, mA, mB);
    reduce_scatter_l0(s, lane, iA0, jA0, iB0, jB0, mk0, mk0, mA, mB);

    // ---- p0 layer 1 accumulate (sk=3) — LAST use of p0 features
    h1_pair(evA, evB, s, 3, hA, hB);
    // prefetch p1 edges while finishing p0 l1
    {
        const float4* pA = (const float4*)(ee + (((size_t)b * NE + iA1) * NE + jA1) * DF);
        const float4* pB = (const float4*)(ee + (((size_t)b * NE + iB1) * NE + jB1) * DF);
        #pragma unroll
        for (int u = 0; u < 8; u++) { evA[u] = pA[u]; evB[u] = pB[u]; }
    }
    finish_pair(hA, hB, s, 3, mA, mB);
    store_wf1(s, iA0, jA0, mk0, mA);
    store_wf1(s, iB0, jB0, mk0, mB);

    // ---- p1 layer 0 (sk=1)
    h1_pair(evA, evB, s, 1, hA, hB);
    finish_pair(hA, hB, s, 1, mA, mB);
    reduce_scatter_l0(s, lane, iA1, jA1, iB1, jB1, 1.f, 1.f, mA, mB);

    // ---- p1 layer 1 accumulate (sk=4) — LAST use of p1 features
    h1_pair(evA, evB, s, 4, hA, hB);
    // prefetch nuclear edge while finishing p1 l1
    {
        const float4* pN = (const float4*)(en + (((size_t)b * NE + iN) * NA + jN) * DF);
        #pragma unroll
        for (int u = 0; u < 8; u++) evA[u] = pN[u];
    }
    finish_pair(hA, hB, s, 4, mA, mB);
    store_wf1(s, iA1, jA1, 1.f, mA);
    store_wf1(s, iB1, jB1, 1.f, mB);

    // ---- nuclear edges: both layers contract with Y
    {
        const float4* yr = (const float4*)(s + OFF_Y + (jN << 3));
        float4 y0 = yr[0], y1 = yr[1];
        #pragma unroll
        for (int l = 0; l < 2; l++) {
            h1_one(evA, s, l * 3 + 2, hA);
            finish_one(hA, s, l * 3 + 2, mA);
            mA[0] *= y0.x; mA[1] *= y0.y; mA[2] *= y0.z; mA[3] *= y0.w;
            mA[4] *= y1.x; mA[5] *= y1.y; mA[6] *= y1.z; mA[7] *= y1.w;
            #pragma unroll
            for (int k = 0; k < 8; k++) {
                #pragma unroll
                for (int d = 1; d < 8; d <<= 1)
                    mA[k] += __shfl_xor_sync(0xffffffffu, mA[k], d);
            }
            if ((lane & 7) == 0) {
                float* zdst = s + ((l == 0) ? OFF_Z0 : OFF_Z1) + (iN << 3);
                #pragma unroll
                for (int k = 0; k < 8; k++) atomicAdd(&zdst[k], mA[k]);
            }
        }
    }
    __syncthreads();

    // ============ layer-0 update: x += Z0 @ gW0 + gb0 ============
    for (int t = tid; t < NE * ED; t += 256) {
        int i = t >> 4, ei = t & 15;
        float a = s[OFF_GB + ei];
        #pragma unroll
        for (int k = 0; k < KD; k++)
            a = fmaf(s[OFF_Z0 + i * KD + k], s[OFF_GW + k * ED + ei], a);
        s[OFF_X + t] += a;
    }
    __syncthreads();

    // hx1[j][k] = ssp(x1[j] @ hW1 + hb1)
    {
        int j = tid >> 3, k = tid & 7;
        float a = s[OFF_HB + KD + k];
        #pragma unroll
        for (int ei = 0; ei < ED; ei++)
            a = fmaf(s[OFF_X + j * ED + ei], s[OFF_HW + (ED + ei) * KD + k], a);
        s[OFF_HX + tid] = sspf(a);
    }
    __syncthreads();

    // z1[i][k] += sum_j WF1[i][j][k] * hx1[j][k]   (Z1 already has nuc part)
    {
        int i = tid >> 3, k = tid & 7;
        float a = s[OFF_Z1 + tid];
        const float* wf = s + OFF_WF1 + (i << 8) + k;
        #pragma unroll
        for (int j = 0; j < NE; j++)
            a = fmaf(wf[j << 3], s[OFF_HX + (j << 3) + k], a);
        s[OFF_Z1 + tid] = a;
    }
    __syncthreads();

    // layer-1 update: x += Z1 @ gW1 + gb1
    for (int t = tid; t < NE * ED; t += 256) {
        int i = t >> 4, ei = t & 15;
        float a = s[OFF_GB + ED + ei];
        #pragma unroll
        for (int k = 0; k < KD; k++)
            a = fmaf(s[OFF_Z1 + i * KD + k], s[OFF_GW + (KD + k) * ED + ei], a);
        s[OFF_X + t] += a;
    }
    __syncthreads();

    // readout
    float part = 0.f;
    for (int t = tid; t < NE * ED; t += 256)
        part += s[OFF_X + t] * s[OFF_ORB + (t & 15)];
    #pragma unroll
    for (int off = 16; off > 0; off >>= 1)
        part += __shfl_down_sync(0xffffffffu, part, off);
    if (lane == 0) atomicAdd(&s[OFF_RED], part);
    __syncthreads();
    if (tid == 0) out[b] = s[OFF_RED];
}

extern "C" void kernel_launch(void* const* d_in, const int* in_sizes, int n_in,
                              void* d_out, int out_size) {
    const float* ee   = (const float*)d_in[0];
    const float* en   = (const float*)d_in[1];
    const float* Xemb = (const float*)d_in[2];
    const float* Yv   = (const float*)d_in[3];
    const float* wW1  = (const float*)d_in[4];
    const float* wb1  = (const float*)d_in[5];
    const float* wW2  = (const float*)d_in[6];
    const float* wb2  = (const float*)d_in[7];
    const float* hW   = (const float*)d_in[8];
    const float* hb   = (const float*)d_in[9];
    const float* gW   = (const float*)d_in[10];
    const float* gb   = (const float*)d_in[11];
    const float* orbW = (const float*)d_in[12];
    float* out = (float*)d_out;

    size_t smem = SMEM_FLOATS * sizeof(float);
    cudaFuncSetAttribute(jastrow_kernel,
                         cudaFuncAttributeMaxDynamicSharedMemorySize, (int)smem);
    jastrow_kernel<<<512, 256, smem>>>(ee, en, Xemb, Yv, wW1, wb1, wW2, wb2,
                                       hW, hb, gW, gb, orbW, out);
}